// round 13
// baseline (speedup 1.0000x reference)
#include <cuda_runtime.h>
#include <cuda_fp16.h>
#include <cstdint>
#include <math.h>

#define BB 2048
#define CC 256
#define TT 512
#define NSLICE 74              // CTAs per i-tile; 2*74 = 148 = one CTA per SM
#define NJOBS (BB * 4)         // (b, t0) jobs per i-tile: 2048 * 4 t-tiles
#define GEMM_THREADS 512
#define CTA_THREADS  576       // 16 GEMM warps + 2 scan warps

// ---------------- device scratch (allocations forbidden) ----------------
__device__ float  g_FF[(size_t)BB * TT * CC];   // FF[b][t][i] fp32 (1 GiB)
__device__ float  g_WrT[CC * CC];               // WrT[j][i] = Wr[i][j]
__device__ int    g_done[BB];                   // per-batch job completion (target 8)
__device__ int    g_scan_next;                  // scan work queue counter

// ---------------- helpers ----------------
__device__ __forceinline__ uint32_t smem_u32(const void* p) {
    uint32_t a;
    asm("{ .reg .u64 t; cvta.to.shared.u64 t, %1; cvt.u32.u64 %0, t; }" : "=r"(a) : "l"(p));
    return a;
}
__device__ __forceinline__ int ld_acquire(const int* p) {
    int v;
    asm volatile("ld.global.acquire.gpu.b32 %0, [%1];" : "=r"(v) : "l"(p) : "memory");
    return v;
}
#define BAR_GEMM() asm volatile("bar.sync 1, %0;" :: "n"(GEMM_THREADS) : "memory")

#define LDSM4(R, addr) \
    asm volatile("ldmatrix.sync.aligned.m8n8.x4.shared.b16 {%0,%1,%2,%3}, [%4];" \
        : "=r"((R)[0]), "=r"((R)[1]), "=r"((R)[2]), "=r"((R)[3]) : "r"(addr))

#define LDSM4T(R, addr) \
    asm volatile("ldmatrix.sync.aligned.m8n8.x4.trans.shared.b16 {%0,%1,%2,%3}, [%4];" \
        : "=r"((R)[0]), "=r"((R)[1]), "=r"((R)[2]), "=r"((R)[3]) : "r"(addr))

#define MMA16816(C, A, B) \
    asm volatile("mma.sync.aligned.m16n8k16.row.col.f32.f16.f16.f32 " \
        "{%0,%1,%2,%3}, {%4,%5,%6,%7}, {%8,%9}, {%0,%1,%2,%3};" \
        : "+f"((C)[0]), "+f"((C)[1]), "+f"((C)[2]), "+f"((C)[3]) \
        : "r"((A)[0]), "r"((A)[1]), "r"((A)[2]), "r"((A)[3]), "r"((B)[0]), "r"((B)[1]))

// A tile swizzle ([c][t], 256B rows): XOR bits[6:4] with bits[10:8]
__device__ __forceinline__ uint32_t swzA(uint32_t off) { return off ^ (((off >> 8) & 7) << 4); }
// B resident tile: [i][c], 512B rows; chunk-column XOR row for conflict-free LDSM
__device__ __forceinline__ uint32_t boff_f(int row, int c16) {
    return (uint32_t)(row * 512 + (((uint32_t)c16 ^ ((uint32_t)row & 7)) << 4));
}

// ---------------- Wr transpose + flag reset (graph-replay safe) ----------------
__global__ void convert_w_kernel(const float* __restrict__ Wr) {
    int i = blockIdx.x;
    int c = threadIdx.x;
    g_WrT[c * CC + i] = Wr[i * CC + c];
    int idx = blockIdx.x * 256 + threadIdx.x;
    if (idx < BB) g_done[idx] = 0;
    if (idx == BB) g_scan_next = 0;
}

// ---------------- scan of one batch by one warp (R9 champion body) ----------------
__device__ __forceinline__ void scan_batch(int w, int lane, float* __restrict__ out) {
    const float DECAY = (float)(1.0 - 1.0 / 6.0);
    const float VTH   = 3.0f;
    const int   KEY_VTH = 0x40400000;

    const float* ffb = g_FF + (size_t)w * TT * CC + lane * 8;

    float v[8], f[8], wr[8];
#pragma unroll
    for (int j = 0; j < 8; j++) v[j] = 0.0f;
    bool has_r = false;

    {
        float4 f0 = *(const float4*)(ffb);
        float4 f1 = *(const float4*)(ffb + 4);
        f[0]=f0.x; f[1]=f0.y; f[2]=f0.z; f[3]=f0.w;
        f[4]=f1.x; f[5]=f1.y; f[6]=f1.z; f[7]=f1.w;
    }

    for (int t = 0; t < TT - 1; t++) {
        float4 n0 = *(const float4*)(ffb + (size_t)(t + 1) * CC);
        float4 n1 = *(const float4*)(ffb + (size_t)(t + 1) * CC + 4);

        if (has_r) {
#pragma unroll
            for (int j = 0; j < 8; j++) v[j] = v[j] * DECAY + f[j] + wr[j];
        } else {
#pragma unroll
            for (int j = 0; j < 8; j++) v[j] = v[j] * DECAY + f[j];
        }

        float m = v[0];
        int   mi = 0;
#pragma unroll
        for (int j = 1; j < 8; j++)
            if (v[j] > m) { m = v[j]; mi = j; }

        int s = __float_as_int(m);
        int key = s ^ ((s >> 31) & 0x7fffffff);
        int kmax;
        asm volatile("redux.sync.max.s32 %0, %1, 0xffffffff;" : "=r"(kmax) : "r"(key));
        unsigned ball = __ballot_sync(0xffffffffu, key == kmax);
        int src = __ffs(ball) - 1;
        int gi  = __shfl_sync(0xffffffffu, lane * 8 + mi, src);

        bool fired = (kmax >= KEY_VTH);
        if (fired) {
            const float4* wp = (const float4*)(g_WrT + gi * CC + lane * 8);
            float4 r0 = wp[0];
            float4 r1 = wp[1];
            wr[0]=r0.x; wr[1]=r0.y; wr[2]=r0.z; wr[3]=r0.w;
            wr[4]=r1.x; wr[5]=r1.y; wr[6]=r1.z; wr[7]=r1.w;
        }
        has_r = fired;

#pragma unroll
        for (int j = 0; j < 8; j++)
            if (v[j] >= VTH) v[j] = 0.0f;

        f[0]=n0.x; f[1]=n0.y; f[2]=n0.z; f[3]=n0.w;
        f[4]=n1.x; f[5]=n1.y; f[6]=n1.z; f[7]=n1.w;
    }

    if (has_r) {
#pragma unroll
        for (int j = 0; j < 8; j++) v[j] = v[j] * DECAY + f[j] + wr[j];
    } else {
#pragma unroll
        for (int j = 0; j < 8; j++) v[j] = v[j] * DECAY + f[j];
    }

    float* op = out + (size_t)w * CC + lane * 8;
    float4 o0 = {expf(v[0]), expf(v[1]), expf(v[2]), expf(v[3])};
    float4 o1 = {expf(v[4]), expf(v[5]), expf(v[6]), expf(v[7])};
    *(float4*)op       = o0;
    *(float4*)(op + 4) = o1;
}

// ---------------- fused persistent GEMM + overlapped scan ----------------
#define SM_B_H  0
#define SM_B_L  65536
#define SM_A    131072          // + stage*32768 ; hi at +0, lo at +16384
#define A_STG   32768
#define SM_TOTAL 196608         // 192 KB

__global__ void __launch_bounds__(CTA_THREADS, 1) fused_kernel(
    const float* __restrict__ x, const float* __restrict__ Wf, float* __restrict__ out) {
    extern __shared__ char smem[];
    uint32_t sbase = smem_u32(smem);

    int tid  = threadIdx.x;
    int lane = tid & 31;
    int wid  = tid >> 5;

    if (wid < 16) {
        // ================= GEMM role (threads 0..511) =================
        int warpM = wid & 3;
        int warpN = wid >> 2;
        int i0 = blockIdx.x * 128;
        int slice = blockIdx.y;

        // prologue: fp32 Wf tile -> fp16 hi/lo resident smem
#pragma unroll
        for (int it = 0; it < 8; it++) {
            int chunk = tid + it * 512;
            int i = chunk >> 5, c16 = chunk & 31;
            const float* wsrc = Wf + (size_t)(i0 + i) * CC + c16 * 8;
            float4 w0 = *(const float4*)(wsrc);
            float4 w1 = *(const float4*)(wsrc + 4);
            float wv[8] = {w0.x, w0.y, w0.z, w0.w, w1.x, w1.y, w1.z, w1.w};
            uint32_t hp[4], lp[4];
#pragma unroll
            for (int q = 0; q < 4; q++) {
                __half h0 = __float2half_rn(wv[q * 2]);
                __half h1 = __float2half_rn(wv[q * 2 + 1]);
                __half l0 = __float2half_rn(wv[q * 2]     - __half2float(h0));
                __half l1 = __float2half_rn(wv[q * 2 + 1] - __half2float(h1));
                hp[q] = (uint32_t)__half_as_ushort(h0) | ((uint32_t)__half_as_ushort(h1) << 16);
                lp[q] = (uint32_t)__half_as_ushort(l0) | ((uint32_t)__half_as_ushort(l1) << 16);
            }
            uint32_t off = boff_f(i, c16);
            *(uint4*)(smem + SM_B_H + off) = make_uint4(hp[0], hp[1], hp[2], hp[3]);
            *(uint4*)(smem + SM_B_L + off) = make_uint4(lp[0], lp[1], lp[2], lp[3]);
        }

        int a_c  = tid >> 5;
        int a_t4 = tid & 31;
        int a_crow = (lane & 7) + ((lane >> 4) << 3);
        int a_t8   = ((lane >> 3) & 1) * 8;
        int b_irow = (lane & 7) + ((lane >> 4) << 3);
        int b_cs   = (lane >> 3) & 1;

        float4 av[4];

#define LOAD_A_REGS(ptr, tt0, kc) do { \
    _Pragma("unroll") \
    for (int it = 0; it < 4; it++) \
        av[it] = *(const float4*)&(ptr)[(size_t)((kc) + a_c + it * 16) * TT + (tt0) + a_t4 * 4]; \
} while (0)

#define STS_A(stage) do { \
    _Pragma("unroll") \
    for (int it = 0; it < 4; it++) { \
        float vv[4] = {av[it].x, av[it].y, av[it].z, av[it].w}; \
        uint32_t hp[2], lp[2]; \
        _Pragma("unroll") \
        for (int q = 0; q < 2; q++) { \
            __half h0 = __float2half_rn(vv[q * 2]); \
            __half h1 = __float2half_rn(vv[q * 2 + 1]); \
            __half l0 = __float2half_rn(vv[q * 2]     - __half2float(h0)); \
            __half l1 = __float2half_rn(vv[q * 2 + 1] - __half2float(h1)); \
            hp[q] = (uint32_t)__half_as_ushort(h0) | ((uint32_t)__half_as_ushort(h1) << 16); \
            lp[q] = (uint32_t)__half_as_ushort(l0) | ((uint32_t)__half_as_ushort(l1) << 16); \
        } \
        uint32_t off = swzA((uint32_t)((a_c + it * 16) * 256 + a_t4 * 8)); \
        *(uint2*)(smem + SM_A + (stage) * A_STG + off)         = make_uint2(hp[0], hp[1]); \
        *(uint2*)(smem + SM_A + (stage) * A_STG + 16384 + off) = make_uint2(lp[0], lp[1]); \
    } \
} while (0)

        int job = slice;
        int b   = job >> 2;
        int t0  = (job & 3) << 7;
        const float* xb = x + (size_t)b * CC * TT;

        LOAD_A_REGS(xb, t0, 0);
        STS_A(0);
        int st = 0;

        for (; job < NJOBS; job += NSLICE) {
            int jobN   = job + NSLICE;
            bool haveN = jobN < NJOBS;
            int bN     = haveN ? (jobN >> 2) : b;
            int t0N    = haveN ? ((jobN & 3) << 7) : t0;
            const float* xbN = x + (size_t)bN * CC * TT;

            float acc[2][4][4];
#pragma unroll
            for (int mf = 0; mf < 2; mf++)
#pragma unroll
                for (int nf = 0; nf < 4; nf++)
#pragma unroll
                    for (int e = 0; e < 4; e++) acc[mf][nf][e] = 0.0f;

#pragma unroll
            for (int k = 0; k < 4; k++) {
                BAR_GEMM();

                if (k < 3)      LOAD_A_REGS(xb, t0, (k + 1) * 64);
                else if (haveN) LOAD_A_REGS(xbN, t0N, 0);

                uint32_t abase = sbase + SM_A + st * A_STG;
#pragma unroll
                for (int k16 = 0; k16 < 4; k16++) {
                    uint32_t ah[2][4], al[2][4], bh[4][2], bl[4][2];
                    int crow = k16 * 16 + a_crow;
#pragma unroll
                    for (int mf = 0; mf < 2; mf++) {
                        uint32_t off = swzA((uint32_t)(crow * 256 + (warpM * 32 + mf * 16 + a_t8) * 2));
                        LDSM4T(ah[mf], abase + off);
                        LDSM4T(al[mf], abase + 16384 + off);
                    }
                    int c16 = k * 8 + k16 * 2 + b_cs;
#pragma unroll
                    for (int p = 0; p < 2; p++) {
                        int row = warpN * 32 + p * 16 + b_irow;
                        uint32_t off = boff_f(row, c16);
                        uint32_t r[4];
                        LDSM4(r, sbase + SM_B_H + off);
                        bh[2 * p][0] = r[0]; bh[2 * p][1] = r[1];
                        bh[2 * p + 1][0] = r[2]; bh[2 * p + 1][1] = r[3];
                        LDSM4(r, sbase + SM_B_L + off);
                        bl[2 * p][0] = r[0]; bl[2 * p][1] = r[1];
                        bl[2 * p + 1][0] = r[2]; bl[2 * p + 1][1] = r[3];
                    }
#pragma unroll
                    for (int p = 0; p < 3; p++) {
#pragma unroll
                        for (int mf = 0; mf < 2; mf++)
#pragma unroll
                            for (int nf = 0; nf < 4; nf++) {
                                if (p == 0) MMA16816(acc[mf][nf], ah[mf], bh[nf]);
                                if (p == 1) MMA16816(acc[mf][nf], ah[mf], bl[nf]);
                                if (p == 2) MMA16816(acc[mf][nf], al[mf], bh[nf]);
                            }
                    }
                }

                if (k < 3 || haveN) STS_A(st ^ 1);
                st ^= 1;
            }

            // epilogue
            int g   = lane >> 2;
            int t4l = lane & 3;
#pragma unroll
            for (int mf = 0; mf < 2; mf++) {
                int t = t0 + warpM * 32 + mf * 16 + g;
#pragma unroll
                for (int nf = 0; nf < 4; nf++) {
                    int i = i0 + warpN * 32 + nf * 8 + t4l * 2;
                    float* p0 = g_FF + ((size_t)b * TT + t) * CC + i;
                    *(float2*)p0 = make_float2(acc[mf][nf][0], acc[mf][nf][1]);
                    *(float2*)(p0 + 8 * CC) = make_float2(acc[mf][nf][2], acc[mf][nf][3]);
                }
            }

            // publish job completion (threadFenceReduction pattern)
            BAR_GEMM();
            if (tid == 0) {
                __threadfence();
                atomicAdd(&g_done[b], 1);
            }

            b = bN; t0 = t0N; xb = xbN;
        }
        // fall through: GEMM warps join the scan pool
    }

    // ================= scan role (warps 16-17 from start; GEMM warps after) ======
    for (;;) {
        int myb;
        if (lane == 0) myb = atomicAdd(&g_scan_next, 1);
        myb = __shfl_sync(0xffffffffu, myb, 0);
        if (myb >= BB) break;
        if (lane == 0) {
            while (ld_acquire(&g_done[myb]) < 8) __nanosleep(128);
        }
        __syncwarp();
        scan_batch(myb, lane, out);
    }
}

// ---------------------------------------------------------------------------
extern "C" void kernel_launch(void* const* d_in, const int* in_sizes, int n_in,
                              void* d_out, int out_size) {
    const float* x  = (const float*)d_in[0];
    const float* Wf = (const float*)d_in[1];
    const float* Wr = (const float*)d_in[2];
    float* out = (float*)d_out;

    cudaFuncSetAttribute(fused_kernel, cudaFuncAttributeMaxDynamicSharedMemorySize, SM_TOTAL);

    convert_w_kernel<<<CC, CC>>>(Wr);
    fused_kernel<<<dim3(2, NSLICE, 1), CTA_THREADS, SM_TOTAL>>>(x, Wf, out);
}

// round 14
// speedup vs baseline: 1.1746x; 1.1746x over previous
#include <cuda_runtime.h>
#include <cuda_fp16.h>
#include <cstdint>
#include <math.h>

#define BB 2048
#define CC 256
#define TT 512
#define NSLICE 74              // CTAs per i-tile; 2*74 = 148 = one CTA per SM
#define NJOBS (BB * 4)         // (b, t0) jobs per i-tile: 2048 * 4 t-tiles

// ---------------- device scratch (allocations forbidden) ----------------
__device__ float  g_FF[(size_t)BB * TT * CC];   // FF[b][t][i] fp32 (1 GiB)
__device__ __half g_Wfh[CC * CC];               // Wf hi fp16, [i][c] (K-major)
__device__ __half g_Wfl[CC * CC];               // Wf lo fp16
__device__ float  g_WrT[CC * CC];               // WrT[j][i] = Wr[i][j]

// ---------------- helpers ----------------
__device__ __forceinline__ uint32_t smem_u32(const void* p) {
    uint32_t a;
    asm("{ .reg .u64 t; cvta.to.shared.u64 t, %1; cvt.u32.u64 %0, t; }" : "=r"(a) : "l"(p));
    return a;
}

#define LDSM4(R, addr) \
    asm volatile("ldmatrix.sync.aligned.m8n8.x4.shared.b16 {%0,%1,%2,%3}, [%4];" \
        : "=r"((R)[0]), "=r"((R)[1]), "=r"((R)[2]), "=r"((R)[3]) : "r"(addr))

#define LDSM4T(R, addr) \
    asm volatile("ldmatrix.sync.aligned.m8n8.x4.trans.shared.b16 {%0,%1,%2,%3}, [%4];" \
        : "=r"((R)[0]), "=r"((R)[1]), "=r"((R)[2]), "=r"((R)[3]) : "r"(addr))

#define MMA16816(C, A, B) \
    asm volatile("mma.sync.aligned.m16n8k16.row.col.f32.f16.f16.f32 " \
        "{%0,%1,%2,%3}, {%4,%5,%6,%7}, {%8,%9}, {%0,%1,%2,%3};" \
        : "+f"((C)[0]), "+f"((C)[1]), "+f"((C)[2]), "+f"((C)[3]) \
        : "r"((A)[0]), "r"((A)[1]), "r"((A)[2]), "r"((A)[3]), "r"((B)[0]), "r"((B)[1]))

// A tile swizzle ([c][t], 256B rows): XOR bits[6:4] with bits[10:8]
__device__ __forceinline__ uint32_t swzA(uint32_t off) { return off ^ (((off >> 8) & 7) << 4); }
// B resident tile: [i][c], 512B rows; chunk-column XOR row for conflict-free LDSM
__device__ __forceinline__ uint32_t boff_f(int row, int c16) {
    return (uint32_t)(row * 512 + (((uint32_t)c16 ^ ((uint32_t)row & 7)) << 4));
}

// ---------------- weight conversion (tiny) ----------------
__global__ void convert_w_kernel(const float* __restrict__ Wf, const float* __restrict__ Wr) {
    int i = blockIdx.x;
    int c = threadIdx.x;
    float w = Wf[i * CC + c];
    __half h = __float2half_rn(w);
    g_Wfh[i * CC + c] = h;
    g_Wfl[i * CC + c] = __float2half_rn(w - __half2float(h));
    g_WrT[c * CC + i] = Wr[i * CC + c];
}

// ---------------- persistent weight-resident HMMA GEMM ----------------
// R9 structure + explicit fragment software pipeline:
//   A fragments double-buffered across k16; B fragments single-buffered with
//   pass regrouping (ah*bh, al*bh, then reload with bl, ah*bl).
#define SM_B_H  0
#define SM_B_L  65536
#define SM_A    131072          // + stage*32768 ; hi at +0, lo at +16384
#define A_STG   32768
#define SM_TOTAL 196608         // 192 KB

__global__ void __launch_bounds__(512, 1) gemm_mma_kernel(const float* __restrict__ x) {
    extern __shared__ char smem[];
    uint32_t sbase = smem_u32(smem);

    int tid  = threadIdx.x;
    int lane = tid & 31;
    int wid  = tid >> 5;
    int warpM = wid & 3;        // 4 warps along t (32 rows each)
    int warpN = wid >> 2;       // 4 warps along i (32 cols each)

    int i0 = blockIdx.x * 128;
    int slice = blockIdx.y;     // 0..73

    // ---- load resident B tile (Wf hi/lo) ----
#pragma unroll
    for (int it = 0; it < 8; it++) {
        int chunk = tid + it * 512;          // 0..4095 (16B chunks)
        int i = chunk >> 5, c16 = chunk & 31;
        uint32_t off = boff_f(i, c16);
        *(uint4*)(smem + SM_B_H + off) = *(const uint4*)(g_Wfh + (size_t)(i0 + i) * CC + c16 * 8);
        *(uint4*)(smem + SM_B_L + off) = *(const uint4*)(g_Wfl + (size_t)(i0 + i) * CC + c16 * 8);
    }

    int a_c  = tid >> 5;
    int a_t4 = tid & 31;
    int a_crow = (lane & 7) + ((lane >> 4) << 3);
    int a_t8   = ((lane >> 3) & 1) * 8;
    int b_irow = (lane & 7) + ((lane >> 4) << 3);
    int b_cs   = (lane >> 3) & 1;

    float4 av[4];
    uint32_t ah[2][2][4], al[2][2][4];   // [buf][mf][reg] A fragments
    uint32_t bfr[4][2];                  // shared B fragment buffer

#define LOAD_A_REGS(ptr, tt0, kc) do { \
    _Pragma("unroll") \
    for (int it = 0; it < 4; it++) \
        av[it] = *(const float4*)&(ptr)[(size_t)((kc) + a_c + it * 16) * TT + (tt0) + a_t4 * 4]; \
} while (0)

#define STS_A(stage) do { \
    _Pragma("unroll") \
    for (int it = 0; it < 4; it++) { \
        float vv[4] = {av[it].x, av[it].y, av[it].z, av[it].w}; \
        uint32_t hp[2], lp[2]; \
        _Pragma("unroll") \
        for (int q = 0; q < 2; q++) { \
            __half h0 = __float2half_rn(vv[q * 2]); \
            __half h1 = __float2half_rn(vv[q * 2 + 1]); \
            __half l0 = __float2half_rn(vv[q * 2]     - __half2float(h0)); \
            __half l1 = __float2half_rn(vv[q * 2 + 1] - __half2float(h1)); \
            hp[q] = (uint32_t)__half_as_ushort(h0) | ((uint32_t)__half_as_ushort(h1) << 16); \
            lp[q] = (uint32_t)__half_as_ushort(l0) | ((uint32_t)__half_as_ushort(l1) << 16); \
        } \
        uint32_t off = swzA((uint32_t)((a_c + it * 16) * 256 + a_t4 * 8)); \
        *(uint2*)(smem + SM_A + (stage) * A_STG + off)         = make_uint2(hp[0], hp[1]); \
        *(uint2*)(smem + SM_A + (stage) * A_STG + 16384 + off) = make_uint2(lp[0], lp[1]); \
    } \
} while (0)

#define LOAD_A_FRAG(buf, abase, k16v) do { \
    int crow = (k16v) * 16 + a_crow; \
    _Pragma("unroll") \
    for (int mf = 0; mf < 2; mf++) { \
        uint32_t off = swzA((uint32_t)(crow * 256 + (warpM * 32 + mf * 16 + a_t8) * 2)); \
        LDSM4T(ah[buf][mf], (abase) + off); \
        LDSM4T(al[buf][mf], (abase) + 16384 + off); \
    } \
} while (0)

#define LOAD_B_FRAG(base_off, c16v) do { \
    _Pragma("unroll") \
    for (int p = 0; p < 2; p++) { \
        int row = warpN * 32 + p * 16 + b_irow; \
        uint32_t off = boff_f(row, (c16v)); \
        uint32_t r[4]; \
        LDSM4(r, sbase + (base_off) + off); \
        bfr[2 * p][0] = r[0]; bfr[2 * p][1] = r[1]; \
        bfr[2 * p + 1][0] = r[2]; bfr[2 * p + 1][1] = r[3]; \
    } \
} while (0)

    int job = slice;
    int b   = job >> 2;
    int t0  = (job & 3) << 7;
    const float* xb = x + (size_t)b * CC * TT;

    LOAD_A_REGS(xb, t0, 0);
    STS_A(0);
    int st = 0;

    for (; job < NJOBS; job += NSLICE) {
        int jobN   = job + NSLICE;
        bool haveN = jobN < NJOBS;
        int bN     = haveN ? (jobN >> 2) : b;
        int t0N    = haveN ? ((jobN & 3) << 7) : t0;
        const float* xbN = x + (size_t)bN * CC * TT;

        float acc[2][4][4];
#pragma unroll
        for (int mf = 0; mf < 2; mf++)
#pragma unroll
            for (int nf = 0; nf < 4; nf++)
#pragma unroll
                for (int e = 0; e < 4; e++) acc[mf][nf][e] = 0.0f;

#pragma unroll
        for (int k = 0; k < 4; k++) {
            __syncthreads();

            if (k < 3)      LOAD_A_REGS(xb, t0, (k + 1) * 64);
            else if (haveN) LOAD_A_REGS(xbN, t0N, 0);

            uint32_t abase = sbase + SM_A + st * A_STG;

            // preload A fragments for k16 = 0
            LOAD_A_FRAG(0, abase, 0);

#pragma unroll
            for (int k16 = 0; k16 < 4; k16++) {
                int cur = k16 & 1;
                int c16 = k * 8 + k16 * 2 + b_cs;

                // B-hi fragments
                LOAD_B_FRAG(SM_B_H, c16);

                // prefetch next k16's A fragments (hides LDSM latency under MMAs)
                if (k16 < 3) LOAD_A_FRAG(cur ^ 1, abase, k16 + 1);

                // passes ah*bh and al*bh (16 MMAs on the bh buffer)
#pragma unroll
                for (int mf = 0; mf < 2; mf++)
#pragma unroll
                    for (int nf = 0; nf < 4; nf++)
                        MMA16816(acc[mf][nf], ah[cur][mf], bfr[nf]);
#pragma unroll
                for (int mf = 0; mf < 2; mf++)
#pragma unroll
                    for (int nf = 0; nf < 4; nf++)
                        MMA16816(acc[mf][nf], al[cur][mf], bfr[nf]);

                // B-lo fragments into the same buffer, then pass ah*bl
                LOAD_B_FRAG(SM_B_L, c16);
#pragma unroll
                for (int mf = 0; mf < 2; mf++)
#pragma unroll
                    for (int nf = 0; nf < 4; nf++)
                        MMA16816(acc[mf][nf], ah[cur][mf], bfr[nf]);
            }

            if (k < 3 || haveN) STS_A(st ^ 1);
            st ^= 1;
        }

        int g   = lane >> 2;
        int t4l = lane & 3;
#pragma unroll
        for (int mf = 0; mf < 2; mf++) {
            int t = t0 + warpM * 32 + mf * 16 + g;
#pragma unroll
            for (int nf = 0; nf < 4; nf++) {
                int i = i0 + warpN * 32 + nf * 8 + t4l * 2;
                float* p0 = g_FF + ((size_t)b * TT + t) * CC + i;
                *(float2*)p0 = make_float2(acc[mf][nf][0], acc[mf][nf][1]);
                *(float2*)(p0 + 8 * CC) = make_float2(acc[mf][nf][2], acc[mf][nf][3]);
            }
        }

        b = bN; t0 = t0N; xb = xbN;
    }
}

// ---------------- sequential LIF + WTA scan (R9 champion, one warp per batch row) ----
__global__ void __launch_bounds__(256) scan_kernel(float* __restrict__ out) {
    const float DECAY = (float)(1.0 - 1.0 / 6.0);
    const float VTH   = 3.0f;
    const int   KEY_VTH = 0x40400000;   // order-preserving int key of +3.0f

    int w    = (int)((blockIdx.x * blockDim.x + threadIdx.x) >> 5);
    int lane = threadIdx.x & 31;
    if (w >= BB) return;

    const float* ffb = g_FF + (size_t)w * TT * CC + lane * 8;

    float v[8], f[8], wr[8];
#pragma unroll
    for (int j = 0; j < 8; j++) v[j] = 0.0f;
    bool has_r = false;

    {   // preload f(0)
        float4 f0 = *(const float4*)(ffb);
        float4 f1 = *(const float4*)(ffb + 4);
        f[0]=f0.x; f[1]=f0.y; f[2]=f0.z; f[3]=f0.w;
        f[4]=f1.x; f[5]=f1.y; f[6]=f1.z; f[7]=f1.w;
    }

    for (int t = 0; t < TT - 1; t++) {
        float4 n0 = *(const float4*)(ffb + (size_t)(t + 1) * CC);
        float4 n1 = *(const float4*)(ffb + (size_t)(t + 1) * CC + 4);

        if (has_r) {
#pragma unroll
            for (int j = 0; j < 8; j++) v[j] = v[j] * DECAY + f[j] + wr[j];
        } else {
#pragma unroll
            for (int j = 0; j < 8; j++) v[j] = v[j] * DECAY + f[j];
        }

        float m = v[0];
        int   mi = 0;
#pragma unroll
        for (int j = 1; j < 8; j++)
            if (v[j] > m) { m = v[j]; mi = j; }

        int s = __float_as_int(m);
        int key = s ^ ((s >> 31) & 0x7fffffff);
        int kmax;
        asm volatile("redux.sync.max.s32 %0, %1, 0xffffffff;" : "=r"(kmax) : "r"(key));
        unsigned ball = __ballot_sync(0xffffffffu, key == kmax);
        int src = __ffs(ball) - 1;
        int gi  = __shfl_sync(0xffffffffu, lane * 8 + mi, src);

        bool fired = (kmax >= KEY_VTH);
        if (fired) {
            const float4* wp = (const float4*)(g_WrT + gi * CC + lane * 8);
            float4 r0 = wp[0];
            float4 r1 = wp[1];
            wr[0]=r0.x; wr[1]=r0.y; wr[2]=r0.z; wr[3]=r0.w;
            wr[4]=r1.x; wr[5]=r1.y; wr[6]=r1.z; wr[7]=r1.w;
        }
        has_r = fired;

#pragma unroll
        for (int j = 0; j < 8; j++)
            if (v[j] >= VTH) v[j] = 0.0f;

        f[0]=n0.x; f[1]=n0.y; f[2]=n0.z; f[3]=n0.w;
        f[4]=n1.x; f[5]=n1.y; f[6]=n1.z; f[7]=n1.w;
    }

    if (has_r) {
#pragma unroll
        for (int j = 0; j < 8; j++) v[j] = v[j] * DECAY + f[j] + wr[j];
    } else {
#pragma unroll
        for (int j = 0; j < 8; j++) v[j] = v[j] * DECAY + f[j];
    }

    float* op = out + (size_t)w * CC + lane * 8;
    float4 o0 = {expf(v[0]), expf(v[1]), expf(v[2]), expf(v[3])};
    float4 o1 = {expf(v[4]), expf(v[5]), expf(v[6]), expf(v[7])};
    *(float4*)op       = o0;
    *(float4*)(op + 4) = o1;
}

// ---------------------------------------------------------------------------
extern "C" void kernel_launch(void* const* d_in, const int* in_sizes, int n_in,
                              void* d_out, int out_size) {
    const float* x  = (const float*)d_in[0];
    const float* Wf = (const float*)d_in[1];
    const float* Wr = (const float*)d_in[2];
    float* out = (float*)d_out;

    cudaFuncSetAttribute(gemm_mma_kernel, cudaFuncAttributeMaxDynamicSharedMemorySize, SM_TOTAL);

    convert_w_kernel<<<CC, CC>>>(Wf, Wr);
    gemm_mma_kernel<<<dim3(2, NSLICE, 1), 512, SM_TOTAL>>>(x);
    scan_kernel<<<(BB * 32) / 256, 256>>>(out);
}

// round 16
// speedup vs baseline: 1.1906x; 1.0136x over previous
#include <cuda_runtime.h>
#include <cuda_fp16.h>
#include <cstdint>
#include <math.h>

#define BB 2048
#define CC 256
#define TT 512
#define NSLICE 74              // CTAs per i-tile; 2*74 = 148 = one CTA per SM
#define NJOBS (BB * 4)         // (b, t0) jobs per i-tile: 2048 * 4 t-tiles

// ---------------- device scratch (allocations forbidden) ----------------
__device__ float  g_FF[(size_t)BB * TT * CC];   // FF[b][t][i] fp32 (1 GiB)
__device__ __half g_Wfh[CC * CC];               // Wf hi fp16, [i][c] (K-major)
__device__ __half g_Wfl[CC * CC];               // Wf lo fp16
__device__ float  g_WrT[CC * CC];               // WrT[j][i] = Wr[i][j]

// ---------------- helpers ----------------
__device__ __forceinline__ uint32_t smem_u32(const void* p) {
    uint32_t a;
    asm("{ .reg .u64 t; cvta.to.shared.u64 t, %1; cvt.u32.u64 %0, t; }" : "=r"(a) : "l"(p));
    return a;
}

#define LDSM4(R, addr) \
    asm volatile("ldmatrix.sync.aligned.m8n8.x4.shared.b16 {%0,%1,%2,%3}, [%4];" \
        : "=r"((R)[0]), "=r"((R)[1]), "=r"((R)[2]), "=r"((R)[3]) : "r"(addr))

#define LDSM4T(R, addr) \
    asm volatile("ldmatrix.sync.aligned.m8n8.x4.trans.shared.b16 {%0,%1,%2,%3}, [%4];" \
        : "=r"((R)[0]), "=r"((R)[1]), "=r"((R)[2]), "=r"((R)[3]) : "r"(addr))

#define MMA16816(C, A, B) \
    asm volatile("mma.sync.aligned.m16n8k16.row.col.f32.f16.f16.f32 " \
        "{%0,%1,%2,%3}, {%4,%5,%6,%7}, {%8,%9}, {%0,%1,%2,%3};" \
        : "+f"((C)[0]), "+f"((C)[1]), "+f"((C)[2]), "+f"((C)[3]) \
        : "r"((A)[0]), "r"((A)[1]), "r"((A)[2]), "r"((A)[3]), "r"((B)[0]), "r"((B)[1]))

// A tile swizzle ([c][t], 256B rows): XOR bits[6:4] with bits[10:8]
__device__ __forceinline__ uint32_t swzA(uint32_t off) { return off ^ (((off >> 8) & 7) << 4); }
// B resident tile: [i][c], 512B rows; chunk-column XOR row for conflict-free LDSM
__device__ __forceinline__ uint32_t boff_f(int row, int c16) {
    return (uint32_t)(row * 512 + (((uint32_t)c16 ^ ((uint32_t)row & 7)) << 4));
}

// ---------------- weight conversion (tiny) ----------------
__global__ void convert_w_kernel(const float* __restrict__ Wf, const float* __restrict__ Wr) {
    int i = blockIdx.x;
    int c = threadIdx.x;
    float w = Wf[i * CC + c];
    __half h = __float2half_rn(w);
    g_Wfh[i * CC + c] = h;
    g_Wfl[i * CC + c] = __float2half_rn(w - __half2float(h));
    g_WrT[c * CC + i] = Wr[i * CC + c];
}

// ---------------- persistent weight-resident HMMA GEMM ----------------
// R14 + fully pipelined fragments: A double-buffered across k16; B-hi
// prefetched one step ahead (resident tile => always valid, wraps with &31);
// B-lo load covered by the 16 bh MMAs. FIX vs R15: __syncthreads() between
// the resident-B store loop and the first bh fragment prime.
#define SM_B_H  0
#define SM_B_L  65536
#define SM_A    131072          // + stage*32768 ; hi at +0, lo at +16384
#define A_STG   32768
#define SM_TOTAL 196608         // 192 KB

__global__ void __launch_bounds__(512, 1) gemm_mma_kernel(const float* __restrict__ x) {
    extern __shared__ char smem[];
    uint32_t sbase = smem_u32(smem);

    int tid  = threadIdx.x;
    int lane = tid & 31;
    int wid  = tid >> 5;
    int warpM = wid & 3;        // 4 warps along t (32 rows each)
    int warpN = wid >> 2;       // 4 warps along i (32 cols each)

    int i0 = blockIdx.x * 128;
    int slice = blockIdx.y;     // 0..73

    // ---- load resident B tile (Wf hi/lo) ----
#pragma unroll
    for (int it = 0; it < 8; it++) {
        int chunk = tid + it * 512;          // 0..4095 (16B chunks)
        int i = chunk >> 5, c16 = chunk & 31;
        uint32_t off = boff_f(i, c16);
        *(uint4*)(smem + SM_B_H + off) = *(const uint4*)(g_Wfh + (size_t)(i0 + i) * CC + c16 * 8);
        *(uint4*)(smem + SM_B_L + off) = *(const uint4*)(g_Wfl + (size_t)(i0 + i) * CC + c16 * 8);
    }
    __syncthreads();   // resident B tile complete before ANY fragment read (R15 bug fix)

    int a_c  = tid >> 5;
    int a_t4 = tid & 31;
    int a_crow = (lane & 7) + ((lane >> 4) << 3);
    int a_t8   = ((lane >> 3) & 1) * 8;
    int b_irow = (lane & 7) + ((lane >> 4) << 3);
    int b_cs   = (lane >> 3) & 1;

    float4 av[4];
    uint32_t ah[2][2][4], al[2][2][4];   // [buf][mf][reg] A fragments
    uint32_t bh[4][2], bl[4][2];         // B fragment buffers

#define LOAD_A_REGS(ptr, tt0, kc) do { \
    _Pragma("unroll") \
    for (int it = 0; it < 4; it++) \
        av[it] = *(const float4*)&(ptr)[(size_t)((kc) + a_c + it * 16) * TT + (tt0) + a_t4 * 4]; \
} while (0)

#define STS_A(stage) do { \
    _Pragma("unroll") \
    for (int it = 0; it < 4; it++) { \
        float vv[4] = {av[it].x, av[it].y, av[it].z, av[it].w}; \
        uint32_t hp[2], lp[2]; \
        _Pragma("unroll") \
        for (int q = 0; q < 2; q++) { \
            __half h0 = __float2half_rn(vv[q * 2]); \
            __half h1 = __float2half_rn(vv[q * 2 + 1]); \
            __half l0 = __float2half_rn(vv[q * 2]     - __half2float(h0)); \
            __half l1 = __float2half_rn(vv[q * 2 + 1] - __half2float(h1)); \
            hp[q] = (uint32_t)__half_as_ushort(h0) | ((uint32_t)__half_as_ushort(h1) << 16); \
            lp[q] = (uint32_t)__half_as_ushort(l0) | ((uint32_t)__half_as_ushort(l1) << 16); \
        } \
        uint32_t off = swzA((uint32_t)((a_c + it * 16) * 256 + a_t4 * 8)); \
        *(uint2*)(smem + SM_A + (stage) * A_STG + off)         = make_uint2(hp[0], hp[1]); \
        *(uint2*)(smem + SM_A + (stage) * A_STG + 16384 + off) = make_uint2(lp[0], lp[1]); \
    } \
} while (0)

#define LOAD_A_FRAG(buf, abase, k16v) do { \
    int crow = (k16v) * 16 + a_crow; \
    _Pragma("unroll") \
    for (int mf = 0; mf < 2; mf++) { \
        uint32_t off = swzA((uint32_t)(crow * 256 + (warpM * 32 + mf * 16 + a_t8) * 2)); \
        LDSM4T(ah[buf][mf], (abase) + off); \
        LDSM4T(al[buf][mf], (abase) + 16384 + off); \
    } \
} while (0)

#define LOAD_B_FRAG(dst, base_off, c16v) do { \
    _Pragma("unroll") \
    for (int p = 0; p < 2; p++) { \
        int row = warpN * 32 + p * 16 + b_irow; \
        uint32_t off = boff_f(row, (c16v)); \
        uint32_t r[4]; \
        LDSM4(r, sbase + (base_off) + off); \
        dst[2 * p][0] = r[0]; dst[2 * p][1] = r[1]; \
        dst[2 * p + 1][0] = r[2]; dst[2 * p + 1][1] = r[3]; \
    } \
} while (0)

    int job = slice;
    int b   = job >> 2;
    int t0  = (job & 3) << 7;
    const float* xb = x + (size_t)b * CC * TT;

    LOAD_A_REGS(xb, t0, 0);
    STS_A(0);
    int st = 0;

    // prime B-hi fragments for the very first k16 step (resident tile, now synced)
    LOAD_B_FRAG(bh, SM_B_H, b_cs);

    for (; job < NJOBS; job += NSLICE) {
        int jobN   = job + NSLICE;
        bool haveN = jobN < NJOBS;
        int bN     = haveN ? (jobN >> 2) : b;
        int t0N    = haveN ? ((jobN & 3) << 7) : t0;
        const float* xbN = x + (size_t)bN * CC * TT;

        float acc[2][4][4];
#pragma unroll
        for (int mf = 0; mf < 2; mf++)
#pragma unroll
            for (int nf = 0; nf < 4; nf++)
#pragma unroll
                for (int e = 0; e < 4; e++) acc[mf][nf][e] = 0.0f;

#pragma unroll
        for (int k = 0; k < 4; k++) {
            __syncthreads();

            if (k < 3)      LOAD_A_REGS(xb, t0, (k + 1) * 64);
            else if (haveN) LOAD_A_REGS(xbN, t0N, 0);

            uint32_t abase = sbase + SM_A + st * A_STG;

            // A fragments for k16 = 0 of this chunk
            LOAD_A_FRAG(0, abase, 0);

#pragma unroll
            for (int k16 = 0; k16 < 4; k16++) {
                int cur = k16 & 1;
                int c16 = k * 8 + k16 * 2 + b_cs;

                // B-lo for this step (covered by the 16 bh MMAs below)
                LOAD_B_FRAG(bl, SM_B_L, c16);

                // prefetch next k16's A fragments
                if (k16 < 3) LOAD_A_FRAG(cur ^ 1, abase, k16 + 1);

                // passes ah*bh and al*bh
#pragma unroll
                for (int mf = 0; mf < 2; mf++)
#pragma unroll
                    for (int nf = 0; nf < 4; nf++)
                        MMA16816(acc[mf][nf], ah[cur][mf], bh[nf]);
#pragma unroll
                for (int mf = 0; mf < 2; mf++)
#pragma unroll
                    for (int nf = 0; nf < 4; nf++)
                        MMA16816(acc[mf][nf], al[cur][mf], bh[nf]);

                // prefetch NEXT step's B-hi (resident tile: wraps across chunks/jobs)
                LOAD_B_FRAG(bh, SM_B_H, (c16 + 2) & 31);

                // pass ah*bl (covers the bh prefetch)
#pragma unroll
                for (int mf = 0; mf < 2; mf++)
#pragma unroll
                    for (int nf = 0; nf < 4; nf++)
                        MMA16816(acc[mf][nf], ah[cur][mf], bl[nf]);
            }

            if (k < 3 || haveN) STS_A(st ^ 1);
            st ^= 1;
        }

        int g   = lane >> 2;
        int t4l = lane & 3;
#pragma unroll
        for (int mf = 0; mf < 2; mf++) {
            int t = t0 + warpM * 32 + mf * 16 + g;
#pragma unroll
            for (int nf = 0; nf < 4; nf++) {
                int i = i0 + warpN * 32 + nf * 8 + t4l * 2;
                float* p0 = g_FF + ((size_t)b * TT + t) * CC + i;
                *(float2*)p0 = make_float2(acc[mf][nf][0], acc[mf][nf][1]);
                *(float2*)(p0 + 8 * CC) = make_float2(acc[mf][nf][2], acc[mf][nf][3]);
            }
        }

        b = bN; t0 = t0N; xb = xbN;
    }
}

// ---------------- sequential LIF + WTA scan (R9 champion, one warp per batch row) ----
__global__ void __launch_bounds__(256) scan_kernel(float* __restrict__ out) {
    const float DECAY = (float)(1.0 - 1.0 / 6.0);
    const float VTH   = 3.0f;
    const int   KEY_VTH = 0x40400000;   // order-preserving int key of +3.0f

    int w    = (int)((blockIdx.x * blockDim.x + threadIdx.x) >> 5);
    int lane = threadIdx.x & 31;
    if (w >= BB) return;

    const float* ffb = g_FF + (size_t)w * TT * CC + lane * 8;

    float v[8], f[8], wr[8];
#pragma unroll
    for (int j = 0; j < 8; j++) v[j] = 0.0f;
    bool has_r = false;

    {   // preload f(0)
        float4 f0 = *(const float4*)(ffb);
        float4 f1 = *(const float4*)(ffb + 4);
        f[0]=f0.x; f[1]=f0.y; f[2]=f0.z; f[3]=f0.w;
        f[4]=f1.x; f[5]=f1.y; f[6]=f1.z; f[7]=f1.w;
    }

    for (int t = 0; t < TT - 1; t++) {
        float4 n0 = *(const float4*)(ffb + (size_t)(t + 1) * CC);
        float4 n1 = *(const float4*)(ffb + (size_t)(t + 1) * CC + 4);

        if (has_r) {
#pragma unroll
            for (int j = 0; j < 8; j++) v[j] = v[j] * DECAY + f[j] + wr[j];
        } else {
#pragma unroll
            for (int j = 0; j < 8; j++) v[j] = v[j] * DECAY + f[j];
        }

        float m = v[0];
        int   mi = 0;
#pragma unroll
        for (int j = 1; j < 8; j++)
            if (v[j] > m) { m = v[j]; mi = j; }

        int s = __float_as_int(m);
        int key = s ^ ((s >> 31) & 0x7fffffff);
        int kmax;
        asm volatile("redux.sync.max.s32 %0, %1, 0xffffffff;" : "=r"(kmax) : "r"(key));
        unsigned ball = __ballot_sync(0xffffffffu, key == kmax);
        int src = __ffs(ball) - 1;
        int gi  = __shfl_sync(0xffffffffu, lane * 8 + mi, src);

        bool fired = (kmax >= KEY_VTH);
        if (fired) {
            const float4* wp = (const float4*)(g_WrT + gi * CC + lane * 8);
            float4 r0 = wp[0];
            float4 r1 = wp[1];
            wr[0]=r0.x; wr[1]=r0.y; wr[2]=r0.z; wr[3]=r0.w;
            wr[4]=r1.x; wr[5]=r1.y; wr[6]=r1.z; wr[7]=r1.w;
        }
        has_r = fired;

#pragma unroll
        for (int j = 0; j < 8; j++)
            if (v[j] >= VTH) v[j] = 0.0f;

        f[0]=n0.x; f[1]=n0.y; f[2]=n0.z; f[3]=n0.w;
        f[4]=n1.x; f[5]=n1.y; f[6]=n1.z; f[7]=n1.w;
    }

    if (has_r) {
#pragma unroll
        for (int j = 0; j < 8; j++) v[j] = v[j] * DECAY + f[j] + wr[j];
    } else {
#pragma unroll
        for (int j = 0; j < 8; j++) v[j] = v[j] * DECAY + f[j];
    }

    float* op = out + (size_t)w * CC + lane * 8;
    float4 o0 = {expf(v[0]), expf(v[1]), expf(v[2]), expf(v[3])};
    float4 o1 = {expf(v[4]), expf(v[5]), expf(v[6]), expf(v[7])};
    *(float4*)op       = o0;
    *(float4*)(op + 4) = o1;
}

// ---------------------------------------------------------------------------
extern "C" void kernel_launch(void* const* d_in, const int* in_sizes, int n_in,
                              void* d_out, int out_size) {
    const float* x  = (const float*)d_in[0];
    const float* Wf = (const float*)d_in[1];
    const float* Wr = (const float*)d_in[2];
    float* out = (float*)d_out;

    cudaFuncSetAttribute(gemm_mma_kernel, cudaFuncAttributeMaxDynamicSharedMemorySize, SM_TOTAL);

    convert_w_kernel<<<CC, CC>>>(Wf, Wr);
    gemm_mma_kernel<<<dim3(2, NSLICE, 1), 512, SM_TOTAL>>>(x);
    scan_kernel<<<(BB * 32) / 256, 256>>>(out);
}